// round 4
// baseline (speedup 1.0000x reference)
#include <cuda_runtime.h>
#include <stdint.h>
#include <math.h>

#define NB 8192
#define ND 128
#define TM 128
#define TN 128
#define TK 16
#define NSPLIT 4
#define MARGIN 0.8f
#define EPSF 1e-6f

// ---------------- device scratch (no allocations allowed) ----------------
__device__ float               g_sq[NB];
__device__ unsigned long long  g_pos[NB];   // packed (ordered_d2 << 32) | (~j) ; argmax
__device__ unsigned long long  g_neg[NB];   // packed (ordered_d2 << 32) | ( j) ; argmin
__device__ float               g_sum;
__device__ int                 g_cnt;

// monotone float -> uint32 map (total order preserved)
__device__ __forceinline__ unsigned int ordf(float f) {
    unsigned int u = __float_as_uint(f);
    return (u & 0x80000000u) ? ~u : (u | 0x80000000u);
}

// ---------------- kernel 1: row squared-norms + scratch init ----------------
__global__ void prep_kernel(const float* __restrict__ emb) {
    int i = blockIdx.x * blockDim.x + threadIdx.x;
    if (i < NB) {
        const float4* row = reinterpret_cast<const float4*>(emb + (size_t)i * ND);
        float s = 0.f;
#pragma unroll
        for (int q = 0; q < ND / 4; q++) {
            float4 v = row[q];
            s += v.x * v.x + v.y * v.y + v.z * v.z + v.w * v.w;
        }
        g_sq[i]  = s;
        g_pos[i] = 0ull;
        g_neg[i] = ~0ull;
    }
    if (i == 0) { g_sum = 0.f; g_cnt = 0; }
}

// ---------------- kernel 2: fused Gram + masked argmax/argmin ----------------
__global__ __launch_bounds__(256) void pair_kernel(const float* __restrict__ emb,
                                                   const int*   __restrict__ labels,
                                                   const int*   __restrict__ sbj) {
    __shared__ float As[TK][TM + 4];
    __shared__ float Bs[TK][TN + 4];
    __shared__ int   rlab[TM], rsbj[TM];
    __shared__ float rsq[TM];
    __shared__ int   clab[TN], csbj[TN];
    __shared__ float csq[TN];

    const int row0 = blockIdx.x * TM;
    const int cbeg = blockIdx.y * (NB / NSPLIT);
    const int ntiles = (NB / NSPLIT) / TN;

    const int tid = threadIdx.x;
    const int tx  = tid & 15;   // 0..15 -> column micro-block
    const int ty  = tid >> 4;   // 0..15 -> row micro-block

    if (tid < TM) {
        rlab[tid] = labels[row0 + tid];
        rsbj[tid] = sbj[row0 + tid];
        rsq[tid]  = g_sq[row0 + tid];
    }

    float posv[8], negv[8];
    int   posj[8], negj[8];
#pragma unroll
    for (int a = 0; a < 8; a++) {
        posv[a] = -INFINITY; negv[a] = INFINITY;
        posj[a] = -1;        negj[a] = -1;
    }

    for (int ct = 0; ct < ntiles; ct++) {
        const int col0 = cbeg + ct * TN;

        __syncthreads();   // previous epilogue done before clab/csq overwrite
        if (tid < TN) {
            clab[tid] = labels[col0 + tid];
            csbj[tid] = sbj[col0 + tid];
            csq[tid]  = g_sq[col0 + tid];
        }

        float c[8][8];
#pragma unroll
        for (int a = 0; a < 8; a++)
#pragma unroll
            for (int b = 0; b < 8; b++) c[a][b] = 0.f;

        for (int kk = 0; kk < ND; kk += TK) {
            __syncthreads();
#pragma unroll
            for (int r = 0; r < 2; r++) {
                int l = tid + r * 256;          // 0..511
                int m = l >> 2;                 // 0..127
                int q = l & 3;                  // float4 index within the TK chunk
                float4 v = *reinterpret_cast<const float4*>(emb + (size_t)(row0 + m) * ND + kk + q * 4);
                As[q * 4 + 0][m] = v.x; As[q * 4 + 1][m] = v.y;
                As[q * 4 + 2][m] = v.z; As[q * 4 + 3][m] = v.w;
                float4 w = *reinterpret_cast<const float4*>(emb + (size_t)(col0 + m) * ND + kk + q * 4);
                Bs[q * 4 + 0][m] = w.x; Bs[q * 4 + 1][m] = w.y;
                Bs[q * 4 + 2][m] = w.z; Bs[q * 4 + 3][m] = w.w;
            }
            __syncthreads();
#pragma unroll
            for (int k = 0; k < TK; k++) {
                float ra[8], rb[8];
#pragma unroll
                for (int a = 0; a < 8; a++) ra[a] = As[k][ty * 8 + a];
#pragma unroll
                for (int b = 0; b < 8; b++) rb[b] = Bs[k][tx * 8 + b];
#pragma unroll
                for (int a = 0; a < 8; a++)
#pragma unroll
                    for (int b = 0; b < 8; b++) c[a][b] += ra[a] * rb[b];
            }
        }

        // epilogue: masked running argmax/argmin (j scanned in increasing order
        // within each thread -> strict compare keeps first occurrence)
#pragma unroll
        for (int a = 0; a < 8; a++) {
            const int   i  = row0 + ty * 8 + a;
            const int   ls = rsbj[ty * 8 + a];
            const int   ll = rlab[ty * 8 + a];
            const float si = rsq[ty * 8 + a];
#pragma unroll
            for (int b = 0; b < 8; b++) {
                const int jj = col0 + tx * 8 + b;
                if (csbj[tx * 8 + b] == ls) {
                    const float d2 = si + csq[tx * 8 + b] - 2.f * c[a][b];
                    if (clab[tx * 8 + b] == ll) {
                        if (jj != i && d2 > posv[a]) { posv[a] = d2; posj[a] = jj; }
                    } else {
                        if (d2 < negv[a]) { negv[a] = d2; negj[a] = jj; }
                    }
                }
            }
        }
    }

    // merge across col-splits and tx-threads via packed atomics
#pragma unroll
    for (int a = 0; a < 8; a++) {
        const int i = row0 + ty * 8 + a;
        if (posj[a] >= 0) {
            unsigned long long key =
                ((unsigned long long)ordf(posv[a]) << 32) | (unsigned long long)(0xFFFFFFFFu - (unsigned)posj[a]);
            atomicMax(&g_pos[i], key);
        }
        if (negj[a] >= 0) {
            unsigned long long key =
                ((unsigned long long)ordf(negv[a]) << 32) | (unsigned long long)(unsigned)negj[a];
            atomicMin(&g_neg[i], key);
        }
    }
}

// ---------------- kernel 3: triplet distances + loss accumulation ----------------
__global__ void triplet_kernel(const float* __restrict__ emb) {
    const int gw   = (blockIdx.x * blockDim.x + threadIdx.x) >> 5;  // one warp per row
    const int lane = threadIdx.x & 31;
    if (gw >= NB) return;

    const unsigned long long kp = g_pos[gw];
    const unsigned long long kn = g_neg[gw];
    if (kp == 0ull || kn == ~0ull) return;   // invalid row

    const int p = (int)(0xFFFFFFFFu - (unsigned)kp);
    const int n = (int)(unsigned)kn;

    const float* ri = emb + (size_t)gw * ND;
    const float* rp = emb + (size_t)p  * ND;
    const float* rn = emb + (size_t)n  * ND;

    float s1 = 0.f, s2 = 0.f;
#pragma unroll
    for (int q = lane; q < ND; q += 32) {
        float e  = ri[q];
        float d1 = e - rp[q] + EPSF; s1 += d1 * d1;   // torch pairwise_distance eps quirk
        float d2 = e - rn[q] + EPSF; s2 += d2 * d2;
    }
#pragma unroll
    for (int o = 16; o > 0; o >>= 1) {
        s1 += __shfl_down_sync(0xFFFFFFFFu, s1, o);
        s2 += __shfl_down_sync(0xFFFFFFFFu, s2, o);
    }
    if (lane == 0) {
        float per = fmaxf(sqrtf(s1) - sqrtf(s2) + MARGIN, 0.f);
        atomicAdd(&g_sum, per);
        atomicAdd(&g_cnt, 1);
    }
}

// ---------------- kernel 4: finalize ----------------
__global__ void finalize_kernel(float* __restrict__ out) {
    int   c = g_cnt;
    float s = g_sum;
    out[0] = (c > 0) ? s / (float)c : 0.f;
}

// ---------------- launch ----------------
extern "C" void kernel_launch(void* const* d_in, const int* in_sizes, int n_in,
                              void* d_out, int out_size) {
    const float* emb    = (const float*)d_in[0];
    const int*   labels = (const int*)d_in[1];
    const int*   sbj    = (const int*)d_in[2];
    float*       out    = (float*)d_out;

    prep_kernel<<<(NB + 255) / 256, 256>>>(emb);
    dim3 grid(NB / TM, NSPLIT);
    pair_kernel<<<grid, 256>>>(emb, labels, sbj);
    triplet_kernel<<<(NB * 32) / 256, 256>>>(emb);
    finalize_kernel<<<1, 1>>>(out);
}

// round 7
// speedup vs baseline: 6.9114x; 6.9114x over previous
#include <cuda_runtime.h>
#include <stdint.h>
#include <math.h>

#define NB 8192
#define ND 128
#define NS 16          // number of subjects
#define TM 128
#define TN 128
#define TK 16
#define MARGIN 0.8f
#define EPSF 1e-6f
#define MAXP (NB + NS*128)   // padded row capacity (each bucket 128-aligned)
#define MAXT 4096            // worst-case tile count (one subject owns all rows)
#define PAIR_GRID 384

// ---------------- device scratch (no allocations allowed) ----------------
__device__ float               g_embp[(size_t)MAXP * ND];  // bucketed embeddings
__device__ float               g_sqp [MAXP];               // bucketed sq-norms
__device__ int                 g_labp[MAXP];               // bucketed labels
__device__ int                 g_perm[MAXP];               // bucket slot -> original row
__device__ int                 g_cnt_s[NS];                // per-subject counts
__device__ int                 g_fill [NS];                // scatter fill cursors
__device__ int                 g_poff [NS];                // 128-aligned bucket offsets
__device__ int                 g_tiles[MAXT];              // packed (s | ti<<8 | tj<<16)
__device__ int                 g_ntiles;
__device__ unsigned long long  g_pos[NB];   // packed (ordered_d2 << 32) | (~j) ; argmax
__device__ unsigned long long  g_neg[NB];   // packed (ordered_d2 << 32) | ( j) ; argmin
__device__ float               g_sum;
__device__ int                 g_cnt;

// monotone float -> uint32 map (total order preserved)
__device__ __forceinline__ unsigned int ordf(float f) {
    unsigned int u = __float_as_uint(f);
    return (u & 0x80000000u) ? ~u : (u | 0x80000000u);
}

// ---------------- k0: zero counters ----------------
__global__ void init_kernel() {
    int t = threadIdx.x;
    if (t < NS) { g_cnt_s[t] = 0; g_fill[t] = 0; }
    if (t == 0) { g_sum = 0.f; g_cnt = 0; }
}

// ---------------- k1: subject histogram + pos/neg sentinel init ----------------
__global__ void count_kernel(const int* __restrict__ sbj) {
    int i = blockIdx.x * blockDim.x + threadIdx.x;
    if (i < NB) {
        atomicAdd(&g_cnt_s[sbj[i]], 1);
        g_pos[i] = 0ull;
        g_neg[i] = ~0ull;
    }
}

// ---------------- k2: bucket offsets + tile worklist ----------------
__global__ void plan_kernel() {
    __shared__ int pad[NS], nt[NS], toff[NS], cshr[NS];
    int t = threadIdx.x;
    if (t < NS) {
        int c = g_cnt_s[t];
        cshr[t] = c;
        int m = (c + 127) >> 7;          // tiles along one dim
        pad[t] = m << 7;                 // padded rows
        nt[t]  = m * m;                  // tiles for this subject
    }
    __syncthreads();
    if (t == 0) {
        int acc = 0, tacc = 0;
        for (int s = 0; s < NS; s++) {
            g_poff[s] = acc;  acc  += pad[s];
            toff[s]   = tacc; tacc += nt[s];
        }
        g_ntiles = tacc;
    }
    __syncthreads();
    if (t < NS) {
        int m = (cshr[t] + 127) >> 7;
        int base = toff[t];
        for (int ti = 0; ti < m; ti++)
            for (int tj = 0; tj < m; tj++)
                g_tiles[base++] = t | (ti << 8) | (tj << 16);
    }
}

// ---------------- k3: scatter rows into buckets (warp per row) + sq norms ----------------
__global__ void scatter_kernel(const float* __restrict__ emb,
                               const int*   __restrict__ labels,
                               const int*   __restrict__ sbj) {
    int gw   = (blockIdx.x * blockDim.x + threadIdx.x) >> 5;  // 0..8191
    int lane = threadIdx.x & 31;
    if (gw >= NB) return;

    int slot = 0;
    if (lane == 0) {
        int s = sbj[gw];
        slot = g_poff[s] + atomicAdd(&g_fill[s], 1);
    }
    slot = __shfl_sync(0xFFFFFFFFu, slot, 0);

    float4 v = reinterpret_cast<const float4*>(emb + (size_t)gw * ND)[lane];
    reinterpret_cast<float4*>(g_embp + (size_t)slot * ND)[lane] = v;

    float s = v.x * v.x + v.y * v.y + v.z * v.z + v.w * v.w;
#pragma unroll
    for (int o = 16; o > 0; o >>= 1) s += __shfl_down_sync(0xFFFFFFFFu, s, o);
    if (lane == 0) {
        g_sqp [slot] = s;
        g_labp[slot] = labels[gw];
        g_perm[slot] = gw;
    }
}

// ---------------- k4: persistent fused Gram + masked argmax/argmin over worklist ----------------
__global__ __launch_bounds__(256) void pair_kernel() {
    __shared__ float As[TK][TM + 4];
    __shared__ float Bs[TK][TN + 4];
    __shared__ int   rlab[TM], rperm[TM];
    __shared__ float rsq[TM];
    __shared__ int   clab[TN], cperm[TN];
    __shared__ float csq[TN];

    const int tid = threadIdx.x;
    const int tx  = tid & 15;   // column micro-block
    const int ty  = tid >> 4;   // row micro-block
    const int ntiles = g_ntiles;

    for (int t = blockIdx.x; t < ntiles; t += gridDim.x) {
        const int desc = g_tiles[t];
        const int s  = desc & 255;
        const int ti = (desc >> 8) & 255;
        const int tj = (desc >> 16) & 255;
        const int n    = g_cnt_s[s];
        const int base = g_poff[s];
        const int rbase = base + ti * TM;   // padded-array slot of tile row 0
        const int cbase = base + tj * TN;

        __syncthreads();   // previous tile's epilogue done before smem overwrite
        if (tid < TM) {
            rlab[tid]  = g_labp[rbase + tid];
            rsq[tid]   = g_sqp [rbase + tid];
            rperm[tid] = g_perm[rbase + tid];
            clab[tid]  = g_labp[cbase + tid];
            csq[tid]   = g_sqp [cbase + tid];
            cperm[tid] = g_perm[cbase + tid];
        }

        float c[8][8];
#pragma unroll
        for (int a = 0; a < 8; a++)
#pragma unroll
            for (int b = 0; b < 8; b++) c[a][b] = 0.f;

        for (int kk = 0; kk < ND; kk += TK) {
            __syncthreads();
#pragma unroll
            for (int r = 0; r < 2; r++) {
                int l = tid + r * 256;          // 0..511
                int m = l >> 2;                 // 0..127
                int q = l & 3;                  // float4 index within TK chunk
                float4 v = *reinterpret_cast<const float4*>(g_embp + (size_t)(rbase + m) * ND + kk + q * 4);
                As[q * 4 + 0][m] = v.x; As[q * 4 + 1][m] = v.y;
                As[q * 4 + 2][m] = v.z; As[q * 4 + 3][m] = v.w;
                float4 w = *reinterpret_cast<const float4*>(g_embp + (size_t)(cbase + m) * ND + kk + q * 4);
                Bs[q * 4 + 0][m] = w.x; Bs[q * 4 + 1][m] = w.y;
                Bs[q * 4 + 2][m] = w.z; Bs[q * 4 + 3][m] = w.w;
            }
            __syncthreads();
#pragma unroll
            for (int k = 0; k < TK; k++) {
                float ra[8], rb[8];
#pragma unroll
                for (int a = 0; a < 8; a++) ra[a] = As[k][ty * 8 + a];
#pragma unroll
                for (int b = 0; b < 8; b++) rb[b] = Bs[k][tx * 8 + b];
#pragma unroll
                for (int a = 0; a < 8; a++)
#pragma unroll
                    for (int b = 0; b < 8; b++) c[a][b] += ra[a] * rb[b];
            }
        }

        // epilogue: masked running argmax/argmin; pads excluded by local-index bound
#pragma unroll
        for (int a = 0; a < 8; a++) {
            const int il = ti * TM + ty * 8 + a;       // row index within subject
            if (il >= n) continue;                      // pad row: discard
            const int   ll = rlab[ty * 8 + a];
            const float si = rsq [ty * 8 + a];
            const int   io = rperm[ty * 8 + a];         // original row index
            float posv = -INFINITY, negv = INFINITY;
            int   posj = -1,        negj = -1;
#pragma unroll
            for (int b = 0; b < 8; b++) {
                const int jl = tj * TN + tx * 8 + b;   // col index within subject
                if (jl < n) {
                    const float d2 = si + csq[tx * 8 + b] - 2.f * c[a][b];
                    const int jo = cperm[tx * 8 + b];
                    if (clab[tx * 8 + b] == ll) {
                        if (jo != io && d2 > posv) { posv = d2; posj = jo; }
                    } else {
                        if (d2 < negv) { negv = d2; negj = jo; }
                    }
                }
            }
            // merge (tie-break on ORIGINAL index: pos favors smaller j via ~j, neg via j)
            if (posj >= 0) {
                unsigned long long key =
                    ((unsigned long long)ordf(posv) << 32) | (unsigned long long)(0xFFFFFFFFu - (unsigned)posj);
                atomicMax(&g_pos[io], key);
            }
            if (negj >= 0) {
                unsigned long long key =
                    ((unsigned long long)ordf(negv) << 32) | (unsigned long long)(unsigned)negj;
                atomicMin(&g_neg[io], key);
            }
        }
    }
}

// ---------------- k5: triplet distances + loss accumulation ----------------
__global__ void triplet_kernel(const float* __restrict__ emb) {
    const int gw   = (blockIdx.x * blockDim.x + threadIdx.x) >> 5;  // one warp per row
    const int lane = threadIdx.x & 31;
    if (gw >= NB) return;

    const unsigned long long kp = g_pos[gw];
    const unsigned long long kn = g_neg[gw];
    if (kp == 0ull || kn == ~0ull) return;   // invalid row (no pos or no neg)

    const int p = (int)(0xFFFFFFFFu - (unsigned)kp);
    const int n = (int)(unsigned)kn;

    const float* ri = emb + (size_t)gw * ND;
    const float* rp = emb + (size_t)p  * ND;
    const float* rn = emb + (size_t)n  * ND;

    float s1 = 0.f, s2 = 0.f;
#pragma unroll
    for (int q = lane; q < ND; q += 32) {
        float e  = ri[q];
        float d1 = e - rp[q] + EPSF; s1 += d1 * d1;   // torch pairwise_distance eps quirk
        float d2 = e - rn[q] + EPSF; s2 += d2 * d2;
    }
#pragma unroll
    for (int o = 16; o > 0; o >>= 1) {
        s1 += __shfl_down_sync(0xFFFFFFFFu, s1, o);
        s2 += __shfl_down_sync(0xFFFFFFFFu, s2, o);
    }
    if (lane == 0) {
        float per = fmaxf(sqrtf(s1) - sqrtf(s2) + MARGIN, 0.f);
        atomicAdd(&g_sum, per);
        atomicAdd(&g_cnt, 1);
    }
}

// ---------------- k6: finalize ----------------
__global__ void finalize_kernel(float* __restrict__ out) {
    int   c = g_cnt;
    float s = g_sum;
    out[0] = (c > 0) ? s / (float)c : 0.f;
}

// ---------------- launch ----------------
extern "C" void kernel_launch(void* const* d_in, const int* in_sizes, int n_in,
                              void* d_out, int out_size) {
    const float* emb    = (const float*)d_in[0];
    const int*   labels = (const int*)d_in[1];
    const int*   sbj    = (const int*)d_in[2];
    float*       out    = (float*)d_out;

    init_kernel   <<<1, 32>>>();
    count_kernel  <<<NB / 256, 256>>>(sbj);
    plan_kernel   <<<1, 32>>>();
    scatter_kernel<<<NB * 32 / 256, 256>>>(emb, labels, sbj);
    pair_kernel   <<<PAIR_GRID, 256>>>();
    triplet_kernel<<<NB * 32 / 256, 256>>>(emb);
    finalize_kernel<<<1, 1>>>(out);
}